// round 1
// baseline (speedup 1.0000x reference)
#include <cuda_runtime.h>
#include <mma.h>

using namespace nvcuda;

#define N_IMG 64
#define C_IN  64
#define H_IN  56
#define W_IN  56
#define K_OUT 128
#define H_OUT 54
#define W_OUT 54
#define PQ    (H_OUT * W_OUT)          /* 2916 */
#define NPQ   (N_IMG * PQ)             /* 186624 */
#define HW_IN (H_IN * W_IN)            /* 3136 */

#define TILE_M  128
#define KCHUNK  32
#define NCHUNKS 18                      /* 9 taps * 2 c-halves */

#define LDA 40                          /* A smem ld (floats), 160B mult of 16 */
#define LDB 136                         /* B smem ld */
#define LDO 132                         /* epilogue staging ld */

/* main-loop region: 128*40 + 32*136 = 9472 floats; epilogue: 128*132 = 16896 floats */
#define SMEM_MAIN_FLOATS 16896
#define SMEM_BYTES (SMEM_MAIN_FLOATS * 4 + TILE_M * 2 * 4)   /* + in_base/out_base */

__device__ signed char g_xi8[(long long)N_IMG * C_IN * H_IN * W_IN];
__device__ float       g_wt[9 * C_IN * K_OUT];   /* [rs][c][ko], tf32-rounded */

/* ---------------- quantize x -> int8 (trunc toward zero after clamp) ------ */
__global__ void quant_kernel(const float* __restrict__ x, int n4) {
    int i = blockIdx.x * blockDim.x + threadIdx.x;
    if (i >= n4) return;
    float4 v = reinterpret_cast<const float4*>(x)[i];
    char4 c;
    c.x = (signed char)fminf(fmaxf(v.x, -128.f), 127.f);
    c.y = (signed char)fminf(fmaxf(v.y, -128.f), 127.f);
    c.z = (signed char)fminf(fmaxf(v.z, -128.f), 127.f);
    c.w = (signed char)fminf(fmaxf(v.w, -128.f), 127.f);
    reinterpret_cast<char4*>(g_xi8)[i] = c;
}

/* ---------------- weight transform OIHW -> [rs][c][ko], tf32-rounded ------ */
__global__ void wtrans_kernel(const float* __restrict__ w) {
    int i = blockIdx.x * blockDim.x + threadIdx.x;
    if (i >= 9 * C_IN * K_OUT) return;
    int ko = i & (K_OUT - 1);
    int t  = i >> 7;            /* /K_OUT */
    int c  = t % C_IN;
    int rs = t / C_IN;
    int r = rs / 3, s = rs % 3;
    float v = w[((ko * C_IN + c) * 3 + r) * 3 + s];
    g_wt[i] = wmma::__float_to_tf32(v);   /* round-to-nearest tf32 */
}

/* ---------------- implicit-GEMM conv, wmma tf32 m16n16k8 ------------------ */
extern __shared__ float smem_f[];

__global__ void __launch_bounds__(256) conv_kernel(const float* __restrict__ bias,
                                                   float* __restrict__ out) {
    float* As = smem_f;                       /* [128][LDA] */
    float* Bs = smem_f + TILE_M * LDA;        /* [32][LDB]  */
    float* Os = smem_f;                       /* [128][LDO] epilogue reuse */
    int*  in_base  = (int*)(smem_f + SMEM_MAIN_FLOATS);
    int*  out_base = in_base + TILE_M;

    const int tid = threadIdx.x;
    const int tile0 = blockIdx.x * TILE_M;

    /* per-pixel base offsets (pixels are linear in n*PQ + p*W_OUT + q) */
    for (int m = tid; m < TILE_M; m += 256) {
        int gm  = tile0 + m;
        int n   = gm / PQ;
        int rem = gm - n * PQ;
        int p   = rem / W_OUT;
        int q   = rem - p * W_OUT;
        in_base[m]  = (n * C_IN * H_IN + p) * W_IN + q;   /* x[n][0][p][q]   */
        out_base[m] = n * (K_OUT * PQ) + rem;             /* out[n][0][p][q] */
    }

    wmma::fragment<wmma::accumulator, 16, 16, 8, float> acc[4][2];
    #pragma unroll
    for (int fm = 0; fm < 4; fm++)
        #pragma unroll
        for (int fn = 0; fn < 2; fn++)
            wmma::fill_fragment(acc[fm][fn], 0.0f);

    const int warp_m = (tid >> 5) & 1;   /* 2 warps along M (64 rows each)  */
    const int warp_n = (tid >> 6);       /* 4 warps along N (32 cols each)  */

    for (int chunk = 0; chunk < NCHUNKS; chunk++) {
        int rs = chunk >> 1;
        int c0 = (chunk & 1) * KCHUNK;
        int r = rs / 3, s = rs - (rs / 3) * 3;
        int tap_off = r * W_IN + s;

        __syncthreads();   /* previous chunk's MMAs done before overwrite */

        /* A: 128 pixels x 32 channels (int8 -> float) */
        #pragma unroll
        for (int i = tid; i < TILE_M * KCHUNK; i += 256) {
            int m = i & (TILE_M - 1);
            int c = i >> 7;
            As[m * LDA + c] =
                (float)g_xi8[in_base[m] + (c0 + c) * HW_IN + tap_off];
        }
        /* B: 32 x 128 contiguous float4 from transformed weights */
        const float4* src =
            reinterpret_cast<const float4*>(g_wt + (rs * C_IN + c0) * K_OUT);
        #pragma unroll
        for (int i = tid; i < (KCHUNK * K_OUT) / 4; i += 256) {
            float4 v = src[i];
            int c  = (i * 4) >> 7;
            int ko = (i * 4) & (K_OUT - 1);
            float* d = &Bs[c * LDB + ko];
            d[0] = v.x; d[1] = v.y; d[2] = v.z; d[3] = v.w;
        }
        __syncthreads();

        #pragma unroll
        for (int kk = 0; kk < KCHUNK / 8; kk++) {
            wmma::fragment<wmma::matrix_a, 16, 16, 8, wmma::precision::tf32,
                           wmma::row_major> a[4];
            wmma::fragment<wmma::matrix_b, 16, 16, 8, wmma::precision::tf32,
                           wmma::row_major> b[2];
            #pragma unroll
            for (int fm = 0; fm < 4; fm++)
                wmma::load_matrix_sync(
                    a[fm], &As[(warp_m * 64 + fm * 16) * LDA + kk * 8], LDA);
            #pragma unroll
            for (int fn = 0; fn < 2; fn++)
                wmma::load_matrix_sync(
                    b[fn], &Bs[(kk * 8) * LDB + warp_n * 32 + fn * 16], LDB);
            #pragma unroll
            for (int fm = 0; fm < 4; fm++)
                #pragma unroll
                for (int fn = 0; fn < 2; fn++)
                    wmma::mma_sync(acc[fm][fn], a[fm], b[fn], acc[fm][fn]);
        }
    }

    /* ------- epilogue: stage [ko][m] in smem, coalesced NCHW store -------- */
    __syncthreads();
    #pragma unroll
    for (int fm = 0; fm < 4; fm++)
        #pragma unroll
        for (int fn = 0; fn < 2; fn++) {
            int m0 = warp_m * 64 + fm * 16;
            int n0 = warp_n * 32 + fn * 16;
            wmma::store_matrix_sync(&Os[n0 * LDO + m0], acc[fm][fn], LDO,
                                    wmma::mem_col_major);
        }
    __syncthreads();

    for (int i = tid; i < TILE_M * K_OUT; i += 256) {
        int ko = i >> 7;
        int m  = i & (TILE_M - 1);
        out[out_base[m] + ko * PQ] = Os[ko * LDO + m] + __ldg(&bias[ko]);
    }
}

/* --------------------------------------------------------------------------*/
extern "C" void kernel_launch(void* const* d_in, const int* in_sizes, int n_in,
                              void* d_out, int out_size) {
    const float* x    = (const float*)d_in[0];
    const float* w    = (const float*)d_in[1];
    const float* bias = (const float*)d_in[2];
    float* out = (float*)d_out;

    cudaFuncSetAttribute(conv_kernel,
                         cudaFuncAttributeMaxDynamicSharedMemorySize,
                         SMEM_BYTES);

    int n4 = (N_IMG * C_IN * H_IN * W_IN) / 4;
    quant_kernel<<<(n4 + 255) / 256, 256>>>(x, n4);

    int nw = 9 * C_IN * K_OUT;
    wtrans_kernel<<<(nw + 255) / 256, 256>>>(w);

    conv_kernel<<<NPQ / TILE_M, 256, SMEM_BYTES>>>(bias, out);
}